// round 1
// baseline (speedup 1.0000x reference)
#include <cuda_runtime.h>

// OpticalFlow dense_image_warp: image [8,512,512,16] f32, flow [8,512,512,2] f32
// out[b,y,x,c] = bilinear sample of image at (y - flow[...,0], x - flow[...,1])
// floor clamped to [0, 510], frac clamped to [0,1] (edge clamp), per reference.

#define B 8
#define H 512
#define W 512
#define HW (H * W)
#define NPIX (B * HW)

__global__ __launch_bounds__(256) void warp_kernel(
    const float* __restrict__ image,
    const float* __restrict__ flow,
    float* __restrict__ out)
{
    int t = blockIdx.x * blockDim.x + threadIdx.x;
    if (t >= NPIX) return;

    int b = t >> 18;          // t / (512*512)
    int p = t & (HW - 1);
    int y = p >> 9;           // p / 512
    int x = p & 511;

    float2 f = __ldg(((const float2*)flow) + t);
    float qy = (float)y - f.x;
    float qx = (float)x - f.y;

    float fy = fminf(fmaxf(floorf(qy), 0.0f), (float)(H - 2));
    float fx = fminf(fmaxf(floorf(qx), 0.0f), (float)(W - 2));
    float ay = fminf(fmaxf(qy - fy, 0.0f), 1.0f);
    float ax = fminf(fmaxf(qx - fx, 0.0f), 1.0f);
    int iy = (int)fy;
    int ix = (int)fx;

    // image pixel (b, iy, ix): offset in float4 units = ((b*HW + iy*W + ix) * 16) / 4
    const float4* base = (const float4*)image + (size_t)b * (HW * 4);
    int o_tl = (iy * W + ix) * 4;
    int o_tr = o_tl + 4;
    int o_bl = o_tl + W * 4;
    int o_br = o_bl + 4;

    float4* outp = (float4*)out + (size_t)t * 4;

#pragma unroll
    for (int g = 0; g < 4; g++) {
        float4 tl = __ldg(base + o_tl + g);
        float4 tr = __ldg(base + o_tr + g);
        float4 bl = __ldg(base + o_bl + g);
        float4 br = __ldg(base + o_br + g);
        float4 r;
        {
            float tp = tl.x + ax * (tr.x - tl.x);
            float bt = bl.x + ax * (br.x - bl.x);
            r.x = tp + ay * (bt - tp);
        }
        {
            float tp = tl.y + ax * (tr.y - tl.y);
            float bt = bl.y + ax * (br.y - bl.y);
            r.y = tp + ay * (bt - tp);
        }
        {
            float tp = tl.z + ax * (tr.z - tl.z);
            float bt = bl.z + ax * (br.z - bl.z);
            r.z = tp + ay * (bt - tp);
        }
        {
            float tp = tl.w + ax * (tr.w - tl.w);
            float bt = bl.w + ax * (br.w - bl.w);
            r.w = tp + ay * (bt - tp);
        }
        outp[g] = r;
    }
}

extern "C" void kernel_launch(void* const* d_in, const int* in_sizes, int n_in,
                              void* d_out, int out_size)
{
    const float* image = (const float*)d_in[0];
    const float* flow  = (const float*)d_in[1];
    float* out = (float*)d_out;

    int threads = 256;
    int blocks = (NPIX + threads - 1) / threads;
    warp_kernel<<<blocks, threads>>>(image, flow, out);
}

// round 3
// speedup vs baseline: 1.8712x; 1.8712x over previous
#include <cuda_runtime.h>

// OpticalFlow dense_image_warp: image [8,512,512,16] f32, flow [8,512,512,2] f32
// out[b,y,x,c] = bilinear sample of image at (y - flow[...,0], x - flow[...,1])
// floor clamped to [0, 510], frac clamped to [0,1] (edge clamp), per reference.
//
// R2: channel-parallel mapping — 4 threads per pixel (one float4 channel-group
// each) so warp-level gather LDG.128s have lane-contiguous addresses, cutting
// L1tex wavefronts ~4x (R1 showed l1tex 87.5% = bottleneck, DRAM only 28.5%).

#define B 8
#define H 512
#define W 512
#define HW (H * W)
#define NPIX (B * HW)
#define NTHREADS_TOTAL (NPIX * 4)

__global__ __launch_bounds__(256) void warp_kernel(
    const float* __restrict__ image,
    const float* __restrict__ flow,
    float* __restrict__ out)
{
    int t = blockIdx.x * blockDim.x + threadIdx.x;

    int pix = t >> 2;        // pixel index in [0, NPIX)
    int g   = t & 3;         // channel group 0..3 (4 floats each)

    int b = pix >> 18;       // pix / (512*512)
    int p = pix & (HW - 1);
    int y = p >> 9;
    int x = p & 511;

    // lanes 4k..4k+3 read the same flow element -> L1 broadcast
    float2 f = __ldg(((const float2*)flow) + pix);
    float qy = (float)y - f.x;
    float qx = (float)x - f.y;

    float fy = fminf(fmaxf(floorf(qy), 0.0f), (float)(H - 2));
    float fx = fminf(fmaxf(floorf(qx), 0.0f), (float)(W - 2));
    float ay = fminf(fmaxf(qy - fy, 0.0f), 1.0f);
    float ax = fminf(fmaxf(qx - fx, 0.0f), 1.0f);
    int iy = (int)fy;
    int ix = (int)fx;

    // float4 units: pixel (b, iy, ix) starts at (b*HW + iy*W + ix)*4
    const float4* base = (const float4*)image + (size_t)b * (HW * 4);
    int o_tl = (iy * W + ix) * 4 + g;
    int o_tr = o_tl + 4;
    int o_bl = o_tl + W * 4;
    int o_br = o_bl + 4;

    float4 tl = __ldg(base + o_tl);
    float4 tr = __ldg(base + o_tr);
    float4 bl = __ldg(base + o_bl);
    float4 br = __ldg(base + o_br);

    float4 r;
    {
        float tp = tl.x + ax * (tr.x - tl.x);
        float bt = bl.x + ax * (br.x - bl.x);
        r.x = tp + ay * (bt - tp);
    }
    {
        float tp = tl.y + ax * (tr.y - tl.y);
        float bt = bl.y + ax * (br.y - bl.y);
        r.y = tp + ay * (bt - tp);
    }
    {
        float tp = tl.z + ax * (tr.z - tl.z);
        float bt = bl.z + ax * (br.z - bl.z);
        r.z = tp + ay * (bt - tp);
    }
    {
        float tp = tl.w + ax * (tr.w - tl.w);
        float bt = bl.w + ax * (br.w - bl.w);
        r.w = tp + ay * (bt - tp);
    }

    ((float4*)out)[t] = r;
}

extern "C" void kernel_launch(void* const* d_in, const int* in_sizes, int n_in,
                              void* d_out, int out_size)
{
    const float* image = (const float*)d_in[0];
    const float* flow  = (const float*)d_in[1];
    float* out = (float*)d_out;

    int threads = 256;
    int blocks = NTHREADS_TOTAL / threads;   // 32768
    warp_kernel<<<blocks, threads>>>(image, flow, out);
}